// round 12
// baseline (speedup 1.0000x reference)
#include <cuda_runtime.h>
#include <cuda_bf16.h>
#include <cstdint>

// upfirdn2d(x, outer([1,3,3,1])*4/64, up=2, pad=(2,1))
// Per-dim: even out 2i = .75*x[i] + .25*x[i-1]; odd out 2i+1 = .75*x[i] + .25*x[i+1]
//
// Persistent single-wave kernel: 1024 CTAs x 128 threads. Each warp processes
// 16 CONSECUTIVE tiles (tile = 4 input rows -> 8 output rows = 4KB output), so
// its 16 bulk stores cover one contiguous 64KB output region. Per-warp
// double-buffered SMEM (2 x 4KB) with pipelined cp.async.bulk stores:
// wait_group.read <= 1 keeps one bulk store in flight while computing the next.

static constexpr int H   = 64;
static constexpr int W   = 64;
static constexpr int OW  = 128;
static constexpr int RPW = 4;                      // input rows per tile
static constexpr int WPB = 4;                      // warps per block
static constexpr int TPW = 16;                     // tiles per warp
static constexpr int WARP_FLOATS = 2 * RPW * OW;   // 1024 floats = 4KB per tile

__global__ __launch_bounds__(128) void upsample_fir_persist_kernel(
    const float* __restrict__ x, float* __restrict__ out)
{
    // 2 buffers x 4KB per warp x 4 warps = 32KB
    __shared__ alignas(128) float stile[WPB * 2 * WARP_FLOATS];

    const int wid  = threadIdx.x >> 5;
    const int lane = threadIdx.x & 31;
    const int warp_g = (blockIdx.x << 2) + wid;    // 0..4095
    const int tile0  = warp_g * TPW;               // first tile (of 65536)

    float* __restrict__ sbuf0 = stile + wid * (2 * WARP_FLOATS);
    const float W0 = 0.75f, W1 = 0.25f;
    const bool l0 = (lane == 0), l31 = (lane == 31);

    #pragma unroll 2
    for (int t = 0; t < TPW; t++) {
        const int gt    = tile0 + t;
        const int plane = gt >> 4;              // 16 tiles per plane
        const int i0    = (gt & 15) * RPW;      // first input row

        float* __restrict__ swarp = sbuf0 + (t & 1) * WARP_FLOATS;
        float* __restrict__ sp    = swarp + 4 * lane;
        const float* __restrict__ xp = x + plane * (H * W) + 2 * lane;

        // Reclaim the buffer used at iteration t-2: its bulk READ must be done.
        if (t >= 2) {
            if (l0)
                asm volatile("cp.async.bulk.wait_group.read 1;" ::: "memory");
            __syncwarp();
        }

        // Load 6 input rows: i0-1 .. i0+4 (zero outside [0,H)).
        float2 r[RPW + 2];
        #pragma unroll
        for (int j = 0; j < RPW + 2; j++) {
            const int row = i0 - 1 + j;
            r[j] = ((unsigned)row < (unsigned)H)
                     ? *reinterpret_cast<const float2*>(xp + row * W)
                     : make_float2(0.f, 0.f);
        }

        // Cross-lane horizontal neighbors (zero at tile edges = zero padding).
        float rp[RPW + 2], rn[RPW + 2];
        #pragma unroll
        for (int j = 0; j < RPW + 2; j++) {
            rp[j] = __shfl_up_sync(0xffffffffu, r[j].y, 1);
            rn[j] = __shfl_down_sync(0xffffffffu, r[j].x, 1);
        }
        if (l0) {
            #pragma unroll
            for (int j = 0; j < RPW + 2; j++) rp[j] = 0.f;
        }
        if (l31) {
            #pragma unroll
            for (int j = 0; j < RPW + 2; j++) rn[j] = 0.f;
        }

        // Horizontal filter each loaded row once.
        float h[RPW + 2][4];
        #pragma unroll
        for (int j = 0; j < RPW + 2; j++) {
            h[j][0] = W0 * r[j].x + W1 * rp[j];
            h[j][1] = W0 * r[j].x + W1 * r[j].y;
            h[j][2] = W0 * r[j].y + W1 * r[j].x;
            h[j][3] = W0 * r[j].y + W1 * rn[j];
        }

        // Vertical blend + stage 8 output rows into this tile's buffer.
        #pragma unroll
        for (int k = 0; k < RPW; k++) {
            float4 e, o;
            e.x = W0 * h[k + 1][0] + W1 * h[k][0];
            e.y = W0 * h[k + 1][1] + W1 * h[k][1];
            e.z = W0 * h[k + 1][2] + W1 * h[k][2];
            e.w = W0 * h[k + 1][3] + W1 * h[k][3];

            o.x = W0 * h[k + 1][0] + W1 * h[k + 2][0];
            o.y = W0 * h[k + 1][1] + W1 * h[k + 2][1];
            o.z = W0 * h[k + 1][2] + W1 * h[k + 2][2];
            o.w = W0 * h[k + 1][3] + W1 * h[k + 2][3];

            *reinterpret_cast<float4*>(sp + (2 * k) * OW)     = e;
            *reinterpret_cast<float4*>(sp + (2 * k + 1) * OW) = o;
        }

        __syncwarp();
        if (l0) {
            // Order this warp's SMEM writes before the async-proxy read.
            asm volatile("fence.proxy.async.shared::cta;" ::: "memory");
            float* gdst = out + (size_t)gt * WARP_FLOATS;  // 4KB sequential
            uint32_t saddr;
            asm("{ .reg .u64 tt; cvta.to.shared.u64 tt, %1; cvt.u32.u64 %0, tt; }"
                : "=r"(saddr) : "l"(swarp));
            asm volatile(
                "cp.async.bulk.global.shared::cta.bulk_group [%0], [%1], %2;"
                :: "l"(gdst), "r"(saddr), "n"((int)(WARP_FLOATS * sizeof(float)))
                : "memory");
            asm volatile("cp.async.bulk.commit_group;" ::: "memory");
        }
    }

    // Before CTA exit (SMEM reuse by later work), all bulk READS must be done.
    if (l0)
        asm volatile("cp.async.bulk.wait_group.read 0;" ::: "memory");
}

extern "C" void kernel_launch(void* const* d_in, const int* in_sizes, int n_in,
                              void* d_out, int out_size)
{
    const float* x = (const float*)d_in[0];
    float* out = (float*)d_out;

    // 65536 tiles total / (4 warps * 16 tiles) = 1024 blocks (single wave).
    upsample_fir_persist_kernel<<<1024, 128>>>(x, out);
}

// round 13
// speedup vs baseline: 1.2678x; 1.2678x over previous
#include <cuda_runtime.h>
#include <cuda_bf16.h>
#include <cstdint>

// upfirdn2d(x, outer([1,3,3,1])*4/64, up=2, pad=(2,1))
// Per-dim: even out 2i = .75*x[i] + .25*x[i-1]; odd out 2i+1 = .75*x[i] + .25*x[i+1]
//
// 128-thread blocks; each warp processes 2 consecutive tiles (tile = 4 input
// rows -> 8 output rows = 4KB) into 2 private SMEM buffers, issuing one
// cp.async.bulk per tile. Tile 1's compute overlaps tile 0's TMA SMEM read;
// a single wait_group.read 0 drains both before warp exit. 32768 warps keep
// the DRAM write queue full (the R12 lesson: warp count >> burst length).

static constexpr int H   = 64;
static constexpr int W   = 64;
static constexpr int OW  = 128;
static constexpr int RPW = 4;                      // input rows per tile
static constexpr int WPB = 4;                      // warps per block
static constexpr int TPW = 2;                      // tiles per warp
static constexpr int WARP_FLOATS = 2 * RPW * OW;   // 1024 floats = 4KB

__global__ __launch_bounds__(128) void upsample_fir_wpipe_kernel(
    const float* __restrict__ x, float* __restrict__ out)
{
    __shared__ alignas(128) float stile[WPB * TPW * WARP_FLOATS];  // 32KB

    const int wid  = threadIdx.x >> 5;
    const int lane = threadIdx.x & 31;
    const int warp_g = (blockIdx.x << 2) + wid;    // 0..32767
    const int tile0  = warp_g * TPW;               // first of 65536 tiles

    float* __restrict__ sbase = stile + wid * (TPW * WARP_FLOATS);
    const float W0 = 0.75f, W1 = 0.25f;
    const bool l0 = (lane == 0), l31 = (lane == 31);

    #pragma unroll
    for (int t = 0; t < TPW; t++) {
        const int gt    = tile0 + t;
        const int plane = gt >> 4;              // 16 tiles per plane
        const int i0    = (gt & 15) * RPW;      // first input row

        float* __restrict__ swarp = sbase + t * WARP_FLOATS;
        float* __restrict__ sp    = swarp + 4 * lane;
        const float* __restrict__ xp = x + plane * (H * W) + 2 * lane;

        // Load 6 input rows: i0-1 .. i0+4 (zero outside [0,H)).
        float2 r[RPW + 2];
        #pragma unroll
        for (int j = 0; j < RPW + 2; j++) {
            const int row = i0 - 1 + j;
            r[j] = ((unsigned)row < (unsigned)H)
                     ? *reinterpret_cast<const float2*>(xp + row * W)
                     : make_float2(0.f, 0.f);
        }

        // Cross-lane horizontal neighbors (zero at tile edges = zero padding).
        float rp[RPW + 2], rn[RPW + 2];
        #pragma unroll
        for (int j = 0; j < RPW + 2; j++) {
            rp[j] = __shfl_up_sync(0xffffffffu, r[j].y, 1);
            rn[j] = __shfl_down_sync(0xffffffffu, r[j].x, 1);
        }
        if (l0) {
            #pragma unroll
            for (int j = 0; j < RPW + 2; j++) rp[j] = 0.f;
        }
        if (l31) {
            #pragma unroll
            for (int j = 0; j < RPW + 2; j++) rn[j] = 0.f;
        }

        // Horizontal filter each loaded row once.
        float h[RPW + 2][4];
        #pragma unroll
        for (int j = 0; j < RPW + 2; j++) {
            h[j][0] = W0 * r[j].x + W1 * rp[j];
            h[j][1] = W0 * r[j].x + W1 * r[j].y;
            h[j][2] = W0 * r[j].y + W1 * r[j].x;
            h[j][3] = W0 * r[j].y + W1 * rn[j];
        }

        // Vertical blend + stage 8 output rows into this tile's buffer.
        #pragma unroll
        for (int k = 0; k < RPW; k++) {
            float4 e, o;
            e.x = W0 * h[k + 1][0] + W1 * h[k][0];
            e.y = W0 * h[k + 1][1] + W1 * h[k][1];
            e.z = W0 * h[k + 1][2] + W1 * h[k][2];
            e.w = W0 * h[k + 1][3] + W1 * h[k][3];

            o.x = W0 * h[k + 1][0] + W1 * h[k + 2][0];
            o.y = W0 * h[k + 1][1] + W1 * h[k + 2][1];
            o.z = W0 * h[k + 1][2] + W1 * h[k + 2][2];
            o.w = W0 * h[k + 1][3] + W1 * h[k + 2][3];

            *reinterpret_cast<float4*>(sp + (2 * k) * OW)     = e;
            *reinterpret_cast<float4*>(sp + (2 * k + 1) * OW) = o;
        }

        __syncwarp();
        if (l0) {
            // Order this warp's SMEM writes before the async-proxy read.
            asm volatile("fence.proxy.async.shared::cta;" ::: "memory");
            float* gdst = out + (size_t)gt * WARP_FLOATS;  // 4KB sequential
            uint32_t saddr;
            asm("{ .reg .u64 tt; cvta.to.shared.u64 tt, %1; cvt.u32.u64 %0, tt; }"
                : "=r"(saddr) : "l"(swarp));
            asm volatile(
                "cp.async.bulk.global.shared::cta.bulk_group [%0], [%1], %2;"
                :: "l"(gdst), "r"(saddr), "n"((int)(WARP_FLOATS * sizeof(float)))
                : "memory");
            asm volatile("cp.async.bulk.commit_group;" ::: "memory");
        }
        // No wait here: tile 1 uses a different buffer, so its compute
        // overlaps tile 0's TMA SMEM read.
    }

    // Drain both SMEM reads before CTA exit (global writes drain async).
    if (l0)
        asm volatile("cp.async.bulk.wait_group.read 0;" ::: "memory");
}

extern "C" void kernel_launch(void* const* d_in, const int* in_sizes, int n_in,
                              void* d_out, int out_size)
{
    const float* x = (const float*)d_in[0];
    float* out = (float*)d_out;

    // 65536 tiles / (4 warps * 2 tiles) = 8192 blocks of 128 threads.
    upsample_fir_wpipe_kernel<<<8192, 128>>>(x, out);
}

// round 15
// speedup vs baseline: 1.2995x; 1.0251x over previous
#include <cuda_runtime.h>
#include <cuda_bf16.h>
#include <cstdint>

// upfirdn2d(x, outer([1,3,3,1])*4/64, up=2, pad=(2,1))
// Per-dim: even out 2i = .75*x[i] + .25*x[i-1]; odd out 2i+1 = .75*x[i] + .25*x[i+1]
//
// 64-thread blocks (2 warps), one warp per 4 input rows (8 output rows = 4KB
// contiguous chunk). Per-warp SMEM slice + per-warp cp.async.bulk sequential
// store; NO block barrier. 8KB SMEM/CTA -> max resident CTAs/warps per SM,
// maximizing the count of independent in-flight bulk-store streams (the one
// variable that has tracked DRAM% across all 12 prior variants).

static constexpr int H   = 64;
static constexpr int W   = 64;
static constexpr int OW  = 128;
static constexpr int RPW = 4;                         // input rows per warp
static constexpr int WPB = 2;                         // warps per block
static constexpr int WARP_FLOATS = 2 * RPW * OW;      // 1024 floats = 4KB

__global__ __launch_bounds__(64) void upsample_fir_wbulk64_kernel(
    const float* __restrict__ x, float* __restrict__ out)
{
    __shared__ alignas(128) float stile[WPB * WARP_FLOATS];  // 8KB

    const int wid  = threadIdx.x >> 5;
    const int lane = threadIdx.x & 31;
    const int gw   = (blockIdx.x << 1) + wid;      // global warp id

    const int plane = gw >> 4;                     // 16 warps per plane
    const int i0    = (gw & 15) * RPW;             // first input row

    const float* __restrict__ xp = x + plane * (H * W) + 2 * lane;
    float* __restrict__ swarp = stile + wid * WARP_FLOATS;
    float* __restrict__ sp    = swarp + 4 * lane;

    // Load 6 input rows: i0-1 .. i0+4 (zero outside [0,H)).
    float2 r[RPW + 2];
    #pragma unroll
    for (int j = 0; j < RPW + 2; j++) {
        const int row = i0 - 1 + j;
        r[j] = ((unsigned)row < (unsigned)H)
                 ? *reinterpret_cast<const float2*>(xp + row * W)
                 : make_float2(0.f, 0.f);
    }

    // Cross-lane horizontal neighbors (zero at tile edges = zero padding).
    float rp[RPW + 2], rn[RPW + 2];
    #pragma unroll
    for (int j = 0; j < RPW + 2; j++) {
        rp[j] = __shfl_up_sync(0xffffffffu, r[j].y, 1);
        rn[j] = __shfl_down_sync(0xffffffffu, r[j].x, 1);
    }
    if (lane == 0) {
        #pragma unroll
        for (int j = 0; j < RPW + 2; j++) rp[j] = 0.f;
    }
    if (lane == 31) {
        #pragma unroll
        for (int j = 0; j < RPW + 2; j++) rn[j] = 0.f;
    }

    const float W0 = 0.75f, W1 = 0.25f;

    // Horizontal filter each loaded row once.
    float h[RPW + 2][4];
    #pragma unroll
    for (int j = 0; j < RPW + 2; j++) {
        h[j][0] = W0 * r[j].x + W1 * rp[j];
        h[j][1] = W0 * r[j].x + W1 * r[j].y;
        h[j][2] = W0 * r[j].y + W1 * r[j].x;
        h[j][3] = W0 * r[j].y + W1 * rn[j];
    }

    // Vertical blend + stage 8 output rows into this warp's SMEM slice.
    #pragma unroll
    for (int k = 0; k < RPW; k++) {
        float4 e, o;
        e.x = W0 * h[k + 1][0] + W1 * h[k][0];
        e.y = W0 * h[k + 1][1] + W1 * h[k][1];
        e.z = W0 * h[k + 1][2] + W1 * h[k][2];
        e.w = W0 * h[k + 1][3] + W1 * h[k][3];

        o.x = W0 * h[k + 1][0] + W1 * h[k + 2][0];
        o.y = W0 * h[k + 1][1] + W1 * h[k + 2][1];
        o.z = W0 * h[k + 1][2] + W1 * h[k + 2][2];
        o.w = W0 * h[k + 1][3] + W1 * h[k + 2][3];

        *reinterpret_cast<float4*>(sp + (2 * k) * OW)     = e;
        *reinterpret_cast<float4*>(sp + (2 * k + 1) * OW) = o;
    }

    __syncwarp();
    if (lane == 0) {
        // Order this warp's generic-proxy SMEM writes before the async read.
        asm volatile("fence.proxy.async.shared::cta;" ::: "memory");
        float* gdst = out + (size_t)gw * WARP_FLOATS;   // 4KB sequential chunk
        uint32_t saddr;
        asm("{ .reg .u64 t; cvta.to.shared.u64 t, %1; cvt.u32.u64 %0, t; }"
            : "=r"(saddr) : "l"(swarp));
        asm volatile(
            "cp.async.bulk.global.shared::cta.bulk_group [%0], [%1], %2;"
            :: "l"(gdst), "r"(saddr), "n"((int)(WARP_FLOATS * sizeof(float)))
            : "memory");
        asm volatile("cp.async.bulk.commit_group;" ::: "memory");
        // Wait ONLY for the SMEM read (CTA-local hazard); the global write
        // drains asynchronously past warp retirement.
        asm volatile("cp.async.bulk.wait_group.read 0;" ::: "memory");
    }
}

extern "C" void kernel_launch(void* const* d_in, const int* in_sizes, int n_in,
                              void* d_out, int out_size)
{
    const float* x = (const float*)d_in[0];
    float* out = (float*)d_out;

    const int n_warps = 16 * 256 * (H / RPW);     // 65536
    const int threads = 64;                       // 2 warps/block
    const int blocks  = n_warps / (threads / 32); // 32768

    upsample_fir_wbulk64_kernel<<<blocks, threads>>>(x, out);
}